// round 5
// baseline (speedup 1.0000x reference)
#include <cuda_runtime.h>

// Shapes fixed by dataset: b=8, n=1024, m=2048, x_dim=1, c=3, Z=128
#define BB    8
#define NN    1024
#define MM    2048
#define MT    16      // m-rows per block (2 m-groups x 8 rows, warp pairs split n)
#define MREG  8       // m-rows per warp (register-tiled)
#define EPSV  1e-8f
#define LOG2E 1.4426950408889634f

__device__ __forceinline__ float ex2f(float v) {
    float r;
    asm("ex2.approx.ftz.f32 %0, %1;" : "=f"(r) : "f"(v));
    return r;
}

__global__ __launch_bounds__(128, 8)
void enc_kernel(const float* __restrict__ x,
                const float* __restrict__ y,
                const float* __restrict__ t,
                const float* __restrict__ sigma,
                const float* __restrict__ W,
                const float* __restrict__ bfc,
                float* __restrict__ out)
{
    __shared__ float4 sx[NN];          // (p = C0*x^2, q = -2*C0*x, y0, y1)  16KB
    __shared__ float4 red[4][MREG];    // per-warp partials
    __shared__ float4 zfin[MT];        // (density, zn1, zn2, -)

    const int tid  = threadIdx.x;
    const int lane = tid & 31;
    const int wrp  = tid >> 5;                 // 0..3
    const int g    = wrp & 1;                  // m-group (0,1)
    const int h    = wrp >> 1;                 // n-half  (0,1)
    const int blk  = blockIdx.x;
    const int b    = blk >> 7;                 // 128 m-tiles per batch
    const int m_base = (blk & 127) * MT;

    // Per-channel exponents C_c = -0.5*log2(e)/scale_c^2, scale_c = exp(sigma_c)
    const float C0 = -0.5f * LOG2E * __expf(-2.f * sigma[0]);
    const float C1 = -0.5f * LOG2E * __expf(-2.f * sigma[1]);
    const float C2 = -0.5f * LOG2E * __expf(-2.f * sigma[2]);
    const bool fast = (C0 == C1) && (C0 == C2);

    // Precompute per-n (p, q, y0, y1) into shared
    {
        const float*  xb = x + b * NN;
        const float2* yb = reinterpret_cast<const float2*>(y + b * NN * 2);
        #pragma unroll
        for (int i = tid; i < NN; i += 128) {
            float  xv = xb[i];
            float2 yv = yb[i];
            sx[i] = make_float4(C0 * xv * xv, -2.f * C0 * xv, yv.x, yv.y);
        }
    }

    // This warp's 8 m-rows
    const float* tb = t + b * MM + m_base + g * MREG;
    float tm[MREG];
    #pragma unroll
    for (int j = 0; j < MREG; ++j) tm[j] = __ldg(tb + j);

    __syncthreads();

    float a0[MREG], a1[MREG], a2[MREG];
    #pragma unroll
    for (int j = 0; j < MREG; ++j) { a0[j] = 0.f; a1[j] = 0.f; a2[j] = 0.f; }

    const float4* sp = sx + h * (NN / 2) + lane;

    if (fast) {
        // term = exp2(q*t + p); exp2(C0*t^2) factor applied after reduction
        #pragma unroll 4
        for (int i = 0; i < NN / 64; ++i) {            // 16 iterations (half n)
            float4 v = sp[i * 32];                     // coalesced LDS.128, 8-way reuse
            #pragma unroll
            for (int j = 0; j < MREG; ++j) {
                float e = ex2f(fmaf(v.y, tm[j], v.x)); // 8 independent chains
                a0[j] += e;
                a1[j] = fmaf(e, v.z, a1[j]);
                a2[j] = fmaf(e, v.w, a2[j]);
            }
        }
    } else {
        // General per-channel scales: u = C0*(t-x)^2, e_c = exp2(u * C_c/C0)
        float fj[MREG];
        #pragma unroll
        for (int j = 0; j < MREG; ++j) fj[j] = C0 * tm[j] * tm[j];
        const float r1 = C1 / C0, r2 = C2 / C0;
        #pragma unroll 2
        for (int i = 0; i < NN / 64; ++i) {
            float4 v = sp[i * 32];
            #pragma unroll
            for (int j = 0; j < MREG; ++j) {
                float u = fmaf(v.y, tm[j], v.x) + fj[j];
                float e0 = ex2f(u);
                float e1 = ex2f(u * r1);
                float e2 = ex2f(u * r2);
                a0[j] += e0;
                a1[j] = fmaf(e1, v.z, a1[j]);
                a2[j] = fmaf(e2, v.w, a2[j]);
            }
        }
    }

    // Warp butterfly reduction of all 24 accumulators
    #pragma unroll
    for (int off = 16; off; off >>= 1) {
        #pragma unroll
        for (int j = 0; j < MREG; ++j) {
            a0[j] += __shfl_xor_sync(0xffffffffu, a0[j], off);
            a1[j] += __shfl_xor_sync(0xffffffffu, a1[j], off);
            a2[j] += __shfl_xor_sync(0xffffffffu, a2[j], off);
        }
    }

    // Lane j publishes m-row j partial (compile-time indices, no spills)
    #pragma unroll
    for (int j = 0; j < MREG; ++j) {
        if (lane == j) red[wrp][j] = make_float4(a0[j], a1[j], a2[j], 0.f);
    }

    // W + bias into registers (once per thread; column group k4 = lane)
    const int k4 = lane;
    const float4* Wv = reinterpret_cast<const float4*>(W);
    const float4 wa  = __ldg(Wv + 3 * k4);
    const float4 wb  = __ldg(Wv + 3 * k4 + 1);
    const float4 wc  = __ldg(Wv + 3 * k4 + 2);
    const float4 bbv = __ldg(reinterpret_cast<const float4*>(bfc) + k4);

    __syncthreads();

    // Combine the two n-halves, finalize density/normalization
    if (tid < MT) {
        const int gg = tid >> 3, jj = tid & 7;
        float4 pA = red[gg][jj];        // h = 0 (warp gg)
        float4 pB = red[2 + gg][jj];    // h = 1 (warp 2+gg)
        float s0 = pA.x + pB.x;
        float s1 = pA.y + pB.y;
        float s2 = pA.z + pB.z;
        if (fast) {
            float tv = __ldg(t + b * MM + m_base + tid);
            float E0 = ex2f(C0 * tv * tv);
            s0 *= E0; s1 *= E0; s2 *= E0;
        }
        float inv = 1.f / (s0 + EPSV);
        zfin[tid] = make_float4(s0, s1 * inv, s2 * inv, 0.f);
    }
    __syncthreads();

    // Epilogue: out[b, m_base+mi, 4*k4..4*k4+3], coalesced float4 stores
    float4* out4 = reinterpret_cast<float4*>(out);
    const size_t rowbase = (size_t)(b * MM + m_base);
    #pragma unroll
    for (int mi = wrp; mi < MT; mi += 4) {
        float4 z = zfin[mi];     // warp-uniform broadcast LDS
        float4 o;
        o.x = fmaf(z.x, wa.x, fmaf(z.y, wa.y, fmaf(z.z, wa.z, bbv.x)));
        o.y = fmaf(z.x, wa.w, fmaf(z.y, wb.x, fmaf(z.z, wb.y, bbv.y)));
        o.z = fmaf(z.x, wb.z, fmaf(z.y, wb.w, fmaf(z.z, wc.x, bbv.z)));
        o.w = fmaf(z.x, wc.y, fmaf(z.y, wc.z, fmaf(z.z, wc.w, bbv.w)));
        out4[(rowbase + mi) * 32 + k4] = o;
    }
}

extern "C" void kernel_launch(void* const* d_in, const int* in_sizes, int n_in,
                              void* d_out, int out_size)
{
    const float* x     = (const float*)d_in[0];   // (8,1024,1)
    const float* y     = (const float*)d_in[1];   // (8,1024,2)
    const float* t     = (const float*)d_in[2];   // (8,2048,1)
    const float* sigma = (const float*)d_in[3];   // (3,)
    const float* W     = (const float*)d_in[4];   // (128,3)
    const float* bfc   = (const float*)d_in[5];   // (128,)
    float* out = (float*)d_out;                   // (8,2048,128)

    dim3 grid(BB * (MM / MT));   // 1024 blocks
    enc_kernel<<<grid, 128>>>(x, y, t, sigma, W, bfc, out);
}